// round 2
// baseline (speedup 1.0000x reference)
#include <cuda_runtime.h>

// Problem: tet geometry + vertex segment-max.
// Inputs:  d_in[0] vertices  (V=1,000,000 x 3 f32)
//          d_in[1] indices   (T=4,000,000 x 4 i32)
//          d_in[2] tet_density (T f32)
// Output:  d_out = [tet_area (T) | tet_alpha (T) | vert_density (V)] f32

__global__ void zero_verts_kernel(float* __restrict__ vd, int num_verts) {
    int i = blockIdx.x * blockDim.x + threadIdx.x;
    if (i < num_verts) vd[i] = 0.0f;
}

__global__ void tet_kernel(const float* __restrict__ vertices,
                           const int4* __restrict__ indices,
                           const float* __restrict__ tet_density,
                           float* __restrict__ tet_area,
                           float* __restrict__ tet_alpha,
                           int* __restrict__ vert_density_i,  // float bits, all >= 0
                           int num_tets) {
    int t = blockIdx.x * blockDim.x + threadIdx.x;
    if (t >= num_tets) return;

    int4 idx = __ldg(&indices[t]);
    float d  = __ldg(&tet_density[t]);

    // Gather 4 vertices (3 floats each). 12 independent loads -> high MLP.
    const float* p0 = vertices + 3 * (size_t)idx.x;
    const float* p1 = vertices + 3 * (size_t)idx.y;
    const float* p2 = vertices + 3 * (size_t)idx.z;
    const float* p3 = vertices + 3 * (size_t)idx.w;

    float v0x = __ldg(p0 + 0), v0y = __ldg(p0 + 1), v0z = __ldg(p0 + 2);
    float v1x = __ldg(p1 + 0), v1y = __ldg(p1 + 1), v1z = __ldg(p1 + 2);
    float v2x = __ldg(p2 + 0), v2y = __ldg(p2 + 1), v2z = __ldg(p2 + 2);
    float v3x = __ldg(p3 + 0), v3y = __ldg(p3 + 1), v3z = __ldg(p3 + 2);

    // det of edge matrix
    float e1x = v1x - v0x, e1y = v1y - v0y, e1z = v1z - v0z;
    float e2x = v2x - v0x, e2y = v2y - v0y, e2z = v2z - v0z;
    float e3x = v3x - v0x, e3y = v3y - v0y, e3z = v3z - v0z;

    float det = e1x * (e2y * e3z - e2z * e3y)
              - e1y * (e2x * e3z - e2z * e3x)
              + e1z * (e2x * e3y - e2y * e3x);
    float area = fabsf(det) * (1.0f / 6.0f);

    // min squared edge length over all 6 edges
    float d01 = e1x * e1x + e1y * e1y + e1z * e1z;
    float d02 = e2x * e2x + e2y * e2y + e2z * e2z;
    float d03 = e3x * e3x + e3y * e3y + e3z * e3z;
    float ax = v1x - v2x, ay = v1y - v2y, az = v1z - v2z;
    float d12 = ax * ax + ay * ay + az * az;
    float bx = v1x - v3x, by = v1y - v3y, bz = v1z - v3z;
    float d13 = bx * bx + by * by + bz * bz;
    float cx = v2x - v3x, cy = v2y - v3y, cz = v2z - v3z;
    float d23 = cx * cx + cy * cy + cz * cz;

    float m = fminf(fminf(fminf(d01, d02), fminf(d03, d12)), fminf(d13, d23));
    float el = sqrtf(m);
    float alpha = 1.0f - __expf(-d * el);

    tet_area[t]  = area;
    tet_alpha[t] = alpha;

    // vertex segment-max. d >= 0 so int-bit atomicMax == float max (init 0).
    int db = __float_as_int(d);
    atomicMax(&vert_density_i[idx.x], db);
    atomicMax(&vert_density_i[idx.y], db);
    atomicMax(&vert_density_i[idx.z], db);
    atomicMax(&vert_density_i[idx.w], db);
}

extern "C" void kernel_launch(void* const* d_in, const int* in_sizes, int n_in,
                              void* d_out, int out_size) {
    const float* vertices    = (const float*)d_in[0];
    const int4*  indices     = (const int4*)d_in[1];
    const float* tet_density = (const float*)d_in[2];

    int num_verts = in_sizes[0] / 3;     // 1,000,000
    int num_tets  = in_sizes[2];         // 4,000,000

    float* out = (float*)d_out;
    float* tet_area     = out;
    float* tet_alpha    = out + (size_t)num_tets;
    float* vert_density = out + 2 * (size_t)num_tets;

    zero_verts_kernel<<<(num_verts + 255) / 256, 256>>>(vert_density, num_verts);

    int threads = 256;
    int blocks = (num_tets + threads - 1) / threads;
    tet_kernel<<<blocks, threads>>>(vertices, indices, tet_density,
                                    tet_area, tet_alpha,
                                    (int*)vert_density, num_tets);
}

// round 3
// speedup vs baseline: 1.1528x; 1.1528x over previous
#include <cuda_runtime.h>

// Problem: tet geometry + vertex segment-max.
// Inputs:  d_in[0] vertices  (V=1,000,000 x 3 f32)
//          d_in[1] indices   (T=4,000,000 x 4 i32)
//          d_in[2] tet_density (T f32)
// Output:  d_out = [tet_area (T) | tet_alpha (T) | vert_density (V)] f32
//
// R2: gather via 16B-padded vertex scratch (1 LDG.128 per vertex instead of
// 3 LDG.32) -> 3x fewer L1tex wavefronts, 25% fewer L2 sectors on gathers.

#define MAX_VERTS 1000000

__device__ float4 g_verts4[MAX_VERTS];

// Prep: pad vertices to float4 AND zero the vert_density output region.
__global__ void prep_kernel(const float* __restrict__ verts,
                            float* __restrict__ vd, int num_verts) {
    int i = blockIdx.x * blockDim.x + threadIdx.x;
    if (i < num_verts) {
        float x = __ldg(&verts[3 * i + 0]);
        float y = __ldg(&verts[3 * i + 1]);
        float z = __ldg(&verts[3 * i + 2]);
        g_verts4[i] = make_float4(x, y, z, 0.0f);
        vd[i] = 0.0f;
    }
}

__global__ void tet_kernel(const int4* __restrict__ indices,
                           const float* __restrict__ tet_density,
                           float* __restrict__ tet_area,
                           float* __restrict__ tet_alpha,
                           int* __restrict__ vert_density_i,  // float bits, all >= 0
                           int num_tets) {
    int t = blockIdx.x * blockDim.x + threadIdx.x;
    if (t >= num_tets) return;

    int4 idx = __ldg(&indices[t]);
    float d  = __ldg(&tet_density[t]);

    // 4 independent 16B gathers -> high MLP, 1 sector each (16B aligned).
    float4 v0 = g_verts4[idx.x];
    float4 v1 = g_verts4[idx.y];
    float4 v2 = g_verts4[idx.z];
    float4 v3 = g_verts4[idx.w];

    // det of edge matrix
    float e1x = v1.x - v0.x, e1y = v1.y - v0.y, e1z = v1.z - v0.z;
    float e2x = v2.x - v0.x, e2y = v2.y - v0.y, e2z = v2.z - v0.z;
    float e3x = v3.x - v0.x, e3y = v3.y - v0.y, e3z = v3.z - v0.z;

    float det = e1x * (e2y * e3z - e2z * e3y)
              - e1y * (e2x * e3z - e2z * e3x)
              + e1z * (e2x * e3y - e2y * e3x);
    float area = fabsf(det) * (1.0f / 6.0f);

    // min squared edge length over all 6 edges
    float d01 = e1x * e1x + e1y * e1y + e1z * e1z;
    float d02 = e2x * e2x + e2y * e2y + e2z * e2z;
    float d03 = e3x * e3x + e3y * e3y + e3z * e3z;
    float ax = v1.x - v2.x, ay = v1.y - v2.y, az = v1.z - v2.z;
    float d12 = ax * ax + ay * ay + az * az;
    float bx = v1.x - v3.x, by = v1.y - v3.y, bz = v1.z - v3.z;
    float d13 = bx * bx + by * by + bz * bz;
    float cx = v2.x - v3.x, cy = v2.y - v3.y, cz = v2.z - v3.z;
    float d23 = cx * cx + cy * cy + cz * cz;

    float m = fminf(fminf(fminf(d01, d02), fminf(d03, d12)), fminf(d13, d23));
    float el = sqrtf(m);
    float alpha = 1.0f - __expf(-d * el);

    tet_area[t]  = area;
    tet_alpha[t] = alpha;

    // vertex segment-max. d >= 0 so int-bit atomicMax == float max (init 0).
    int db = __float_as_int(d);
    atomicMax(&vert_density_i[idx.x], db);
    atomicMax(&vert_density_i[idx.y], db);
    atomicMax(&vert_density_i[idx.z], db);
    atomicMax(&vert_density_i[idx.w], db);
}

extern "C" void kernel_launch(void* const* d_in, const int* in_sizes, int n_in,
                              void* d_out, int out_size) {
    const float* vertices    = (const float*)d_in[0];
    const int4*  indices     = (const int4*)d_in[1];
    const float* tet_density = (const float*)d_in[2];

    int num_verts = in_sizes[0] / 3;     // 1,000,000
    int num_tets  = in_sizes[2];         // 4,000,000
    if (num_verts > MAX_VERTS) num_verts = MAX_VERTS;  // fixed-shape problem

    float* out = (float*)d_out;
    float* tet_area     = out;
    float* tet_alpha    = out + (size_t)num_tets;
    float* vert_density = out + 2 * (size_t)num_tets;

    prep_kernel<<<(num_verts + 255) / 256, 256>>>(vertices, vert_density, num_verts);

    int threads = 256;
    int blocks = (num_tets + threads - 1) / threads;
    tet_kernel<<<blocks, threads>>>(indices, tet_density,
                                    tet_area, tet_alpha,
                                    (int*)vert_density, num_tets);
}

// round 4
// speedup vs baseline: 1.1742x; 1.0185x over previous
#include <cuda_runtime.h>

// Problem: tet geometry + vertex segment-max.
// Inputs:  d_in[0] vertices  (V=1,000,000 x 3 f32)
//          d_in[1] indices   (T=4,000,000 x 4 i32)
//          d_in[2] tet_density (T f32)
// Output:  d_out = [tet_area (T) | tet_alpha (T) | vert_density (V)] f32
//
// R3: vectorized prep (4 verts/thread, float4 I/O), streaming cache hints
// (.cs) on the streaming reads/writes to protect vertex residency in L2.
// Model: tet kernel sits at the L2 transaction-rate roofline
// (16M gather sectors + 16M RED.MAX + 3.6M streaming sectors ~ 184/cyc).

#define MAX_VERTS 1000000

__device__ float4 g_verts4[MAX_VERTS];

// Prep: pad vertices to float4 AND zero the vert_density output region.
// Each thread: 4 vertices = 3x float4 coalesced loads, 4x float4 stores, 1x float4 zero.
__global__ __launch_bounds__(256) void prep_kernel(const float4* __restrict__ verts4,
                                                   float4* __restrict__ vd4,
                                                   int num_groups) {  // num_verts/4
    int g = blockIdx.x * blockDim.x + threadIdx.x;
    if (g >= num_groups) return;

    float4 a = __ldcs(&verts4[3 * g + 0]);  // v0.x v0.y v0.z v1.x
    float4 b = __ldcs(&verts4[3 * g + 1]);  // v1.y v1.z v2.x v2.y
    float4 c = __ldcs(&verts4[3 * g + 2]);  // v2.z v3.x v3.y v3.z

    g_verts4[4 * g + 0] = make_float4(a.x, a.y, a.z, 0.0f);
    g_verts4[4 * g + 1] = make_float4(a.w, b.x, b.y, 0.0f);
    g_verts4[4 * g + 2] = make_float4(b.z, b.w, c.x, 0.0f);
    g_verts4[4 * g + 3] = make_float4(c.y, c.z, c.w, 0.0f);

    __stcs(&vd4[g], make_float4(0.0f, 0.0f, 0.0f, 0.0f));
}

__global__ __launch_bounds__(256) void tet_kernel(
        const int4* __restrict__ indices,
        const float* __restrict__ tet_density,
        float* __restrict__ tet_area,
        float* __restrict__ tet_alpha,
        int* __restrict__ vert_density_i,  // float bits, all >= 0
        int num_tets) {
    int t = blockIdx.x * blockDim.x + threadIdx.x;
    if (t >= num_tets) return;

    int4 idx = __ldcs(&indices[t]);      // streaming: evict-first
    float d  = __ldcs(&tet_density[t]);  // streaming: evict-first

    // 4 independent 16B gathers -> high MLP, 1 L2 sector each; default policy
    // so vertex lines stay resident in L2.
    float4 v0 = g_verts4[idx.x];
    float4 v1 = g_verts4[idx.y];
    float4 v2 = g_verts4[idx.z];
    float4 v3 = g_verts4[idx.w];

    // det of edge matrix
    float e1x = v1.x - v0.x, e1y = v1.y - v0.y, e1z = v1.z - v0.z;
    float e2x = v2.x - v0.x, e2y = v2.y - v0.y, e2z = v2.z - v0.z;
    float e3x = v3.x - v0.x, e3y = v3.y - v0.y, e3z = v3.z - v0.z;

    float det = e1x * (e2y * e3z - e2z * e3y)
              - e1y * (e2x * e3z - e2z * e3x)
              + e1z * (e2x * e3y - e2y * e3x);
    float area = fabsf(det) * (1.0f / 6.0f);

    // min squared edge length over all 6 edges
    float d01 = e1x * e1x + e1y * e1y + e1z * e1z;
    float d02 = e2x * e2x + e2y * e2y + e2z * e2z;
    float d03 = e3x * e3x + e3y * e3y + e3z * e3z;
    float ax = v1.x - v2.x, ay = v1.y - v2.y, az = v1.z - v2.z;
    float d12 = ax * ax + ay * ay + az * az;
    float bx = v1.x - v3.x, by = v1.y - v3.y, bz = v1.z - v3.z;
    float d13 = bx * bx + by * by + bz * bz;
    float cx = v2.x - v3.x, cy = v2.y - v3.y, cz = v2.z - v3.z;
    float d23 = cx * cx + cy * cy + cz * cz;

    float m = fminf(fminf(fminf(d01, d02), fminf(d03, d12)), fminf(d13, d23));
    float el = sqrtf(m);
    float alpha = 1.0f - __expf(-d * el);

    __stcs(&tet_area[t], area);    // streaming store: evict-first
    __stcs(&tet_alpha[t], alpha);  // streaming store: evict-first

    // vertex segment-max. d >= 0 so int-bit atomicMax == float max (init 0).
    int db = __float_as_int(d);
    atomicMax(&vert_density_i[idx.x], db);
    atomicMax(&vert_density_i[idx.y], db);
    atomicMax(&vert_density_i[idx.z], db);
    atomicMax(&vert_density_i[idx.w], db);
}

extern "C" void kernel_launch(void* const* d_in, const int* in_sizes, int n_in,
                              void* d_out, int out_size) {
    const float* vertices    = (const float*)d_in[0];
    const int4*  indices     = (const int4*)d_in[1];
    const float* tet_density = (const float*)d_in[2];

    int num_verts = in_sizes[0] / 3;     // 1,000,000
    int num_tets  = in_sizes[2];         // 4,000,000
    if (num_verts > MAX_VERTS) num_verts = MAX_VERTS;  // fixed-shape problem

    float* out = (float*)d_out;
    float* tet_area     = out;
    float* tet_alpha    = out + (size_t)num_tets;
    float* vert_density = out + 2 * (size_t)num_tets;

    // num_verts = 1M is divisible by 4; vd region offset (8M floats) is 16B-aligned.
    int num_groups = num_verts / 4;
    prep_kernel<<<(num_groups + 255) / 256, 256>>>(
        (const float4*)vertices, (float4*)vert_density, num_groups);

    int threads = 256;
    int blocks = (num_tets + threads - 1) / threads;
    tet_kernel<<<blocks, threads>>>(indices, tet_density,
                                    tet_area, tet_alpha,
                                    (int*)vert_density, num_tets);
}